// round 15
// baseline (speedup 1.0000x reference)
#include <cuda_runtime.h>
#include <cuda_fp16.h>
#include <math.h>
#include <stdint.h>

#define BB 2
#define NN 2048
#define KK 48
#define CC 128
#define FFD 512
#define BN (BB * NN)
#define EPSLN 1e-5f
#define INV_SCALE (1.0f / 30.0f)

// ---------------- device scratch ----------------
__device__ float g_Pa[BN * CC];   // h_V @ W1a + b1
__device__ float g_Pc[BN * CC];   // h_V @ W1c
__device__ float g_dh[BN * CC];   // masked message sum
// 6 edge weight images (2 sets x 3 layers), 128x128 fp16, HMMA B-fragment order
__device__ __half g_Wimg[6 * 16384];
// FFN weight images: Win (4 ng-slabs x 16384) + Wout (4 kt-slabs x 16384)
__device__ __half g_WimgF[2 * 65536];

__device__ __forceinline__ float gelu_f(float x) {
    return 0.5f * x * (1.0f + erff(x * 0.70710678118654752f));
}
__device__ __forceinline__ uint32_t pack_h2(float a, float b) {
    __half2 h; h.x = __float2half_rn(a); h.y = __float2half_rn(b);
    return *reinterpret_cast<uint32_t*>(&h);
}
__device__ __forceinline__ void mma16816(float c[4], const uint32_t a[4],
                                         uint32_t b0, uint32_t b1) {
    asm volatile(
        "mma.sync.aligned.m16n8k16.row.col.f32.f16.f16.f32 "
        "{%0,%1,%2,%3}, {%4,%5,%6,%7}, {%8,%9}, {%0,%1,%2,%3};"
        : "+f"(c[0]), "+f"(c[1]), "+f"(c[2]), "+f"(c[3])
        : "r"(a[0]), "r"(a[1]), "r"(a[2]), "r"(a[3]), "r"(b0), "r"(b1));
}

// ---------------------------------------------------------------------------
// Weight prep: 6 edge images in HMMA B-fragment order (proven layout).
// ---------------------------------------------------------------------------
__global__ void prep_weights(const float* __restrict__ A0, const float* __restrict__ A1,
                             const float* __restrict__ A2, const float* __restrict__ B0,
                             const float* __restrict__ B1, const float* __restrict__ B2) {
    const float* srcs[6] = {A0, A1, A2, B0, B1, B2};
    int img = blockIdx.x;
    const float* s = srcs[img];
    __half* dst = g_Wimg + (size_t)img * 16384;
    for (int e = threadIdx.x; e < 16384; e += blockDim.x) {
        int k = e >> 7, n = e & 127;
        int kk = k & 15;
        int t = (kk & 7) >> 1, hi8 = kk >> 3, idx = kk & 1;
        int lane = (n & 7) * 4 + t;
        int chunk = (n >> 3) * 8 + (k >> 4);
        dst[chunk * 128 + lane * 4 + hi8 * 2 + idx] = __float2half_rn(s[e]);
    }
}

// FFN weight prep: blockIdx 0 = Win [128,512] (ng-major slabs),
//                  blockIdx 1 = Wout [512,128] (kt-major slabs).
__global__ void prep_ffn_weights(const float* __restrict__ Win,
                                 const float* __restrict__ Wout) {
    if (blockIdx.x == 0) {
        for (int e = threadIdx.x; e < 65536; e += blockDim.x) {
            int k = e >> 9, n = e & 511;          // Win[k][n]
            int ng = n >> 7, n1 = n & 127;
            int kk = k & 15;
            int t = (kk & 7) >> 1, hi8 = kk >> 3, idx = kk & 1;
            int lane = (n1 & 7) * 4 + t;
            int chunk = (n1 >> 3) * 8 + (k >> 4);
            g_WimgF[ng * 16384 + chunk * 128 + lane * 4 + hi8 * 2 + idx] =
                __float2half_rn(Win[e]);
        }
    } else {
        for (int e = threadIdx.x; e < 65536; e += blockDim.x) {
            int k = e >> 7, n = e & 127;          // Wout[k][n]
            int kt = k >> 7, k1 = k & 127;
            int kk = k1 & 15;
            int t = (kk & 7) >> 1, hi8 = kk >> 3, idx = kk & 1;
            int lane = (n & 7) * 4 + t;
            int chunk = (n >> 3) * 8 + (k1 >> 4);
            g_WimgF[65536 + kt * 16384 + chunk * 128 + lane * 4 + hi8 * 2 + idx] =
                __float2half_rn(Wout[e]);
        }
    }
}

// ---------------------------------------------------------------------------
// HMMA edge MLP — unchanged from Round 12 (proven: ~165us each, 2 CTA/SM).
// ---------------------------------------------------------------------------
#define A_STRIDE_W 68
#define A_WORDS (KK * A_STRIDE_W)
#define SMEM_W_BYTES 98304
#define SMEM_EDGE_DYN (SMEM_W_BYTES + A_WORDS * 4)

template <bool EDGE_OUT>
__global__ void __launch_bounds__(384, 2) edge_mma_kernel(
    const float* __restrict__ h_E, const int* __restrict__ E_idx,
    const float* __restrict__ mask_attend, int wset,
    const float* __restrict__ b2v, const float* __restrict__ b3v,
    const float* __restrict__ g3v, const float* __restrict__ b3ln,
    float* __restrict__ outp) {
    extern __shared__ uint32_t smem[];
    uint32_t* smW = smem;
    uint32_t* smA = smem + (SMEM_W_BYTES / 4);

    __shared__ float s_b2[CC], s_b3[CC], s_g3[CC], s_bl[CC];
    __shared__ float s_red[KK * 4 * 2];
    float* s_part = s_red;

    const int tid = threadIdx.x, lane = tid & 31, wid = tid >> 5;
    const int g = lane >> 2, t = lane & 3;
    const int mtile = wid >> 2, nchunk = wid & 3;
    const int m0 = mtile * 16, n0 = nchunk * 32;
    const int ntg0 = nchunk * 4;

    {
        const float4* src = (const float4*)(g_Wimg + (size_t)wset * 3 * 16384);
        float4* dst = (float4*)smW;
        for (int i = tid; i < 6144; i += 384) dst[i] = src[i];
    }
    if (tid < CC) {
        s_b2[tid] = b2v[tid];
        s_b3[tid] = b3v[tid];
        if (EDGE_OUT) { s_g3[tid] = g3v[tid]; s_bl[tid] = b3ln[tid]; }
    }

    const int r_lo = m0 + g, r_hi = m0 + g + 8;

    for (int node = blockIdx.x; node < BN; node += gridDim.x) {
        __syncthreads();

#pragma unroll
        for (int i = 0; i < 4; ++i) {
            int idx4 = tid + 384 * i;
            float4 v = ((const float4*)(h_E + (size_t)node * (KK * CC)))[idx4];
            int row = idx4 >> 5, colw = (idx4 & 31) * 2;
            int w = row * A_STRIDE_W + colw;
            smA[w] = pack_h2(v.x, v.y);
            smA[w + 1] = pack_h2(v.z, v.w);
        }
        __syncthreads();

        for (int layer = 0; layer < 3; ++layer) {
            float acc[4][4];
#pragma unroll
            for (int nt = 0; nt < 4; ++nt)
#pragma unroll
                for (int j = 0; j < 4; ++j) acc[nt][j] = 0.0f;

            const uint2* WH = (const uint2*)smW + layer * 4096;
#pragma unroll
            for (int ks = 0; ks < 8; ++ks) {
                uint32_t a[4];
                int aw = r_lo * A_STRIDE_W + ks * 8 + t;
                int aw2 = r_hi * A_STRIDE_W + ks * 8 + t;
                a[0] = smA[aw];     a[1] = smA[aw2];
                a[2] = smA[aw + 4]; a[3] = smA[aw2 + 4];
#pragma unroll
                for (int nt = 0; nt < 4; ++nt) {
                    int chunk = (ntg0 + nt) * 8 + ks;
                    uint2 bh = WH[chunk * 32 + lane];
                    mma16816(acc[nt], a, bh.x, bh.y);
                }
            }
            __syncthreads();

            if (layer < 2) {
                float a0v[4][2], b0v[4][2];
                if (layer == 0) {
                    int gb = (node >> 11) * NN;
                    int nbr0 = gb + E_idx[node * KK + r_lo];
                    int nbr1 = gb + E_idx[node * KK + r_hi];
#pragma unroll
                    for (int nt = 0; nt < 4; ++nt) {
                        int c = n0 + nt * 8 + t * 2;
                        float2 pa = *(const float2*)(g_Pa + (size_t)node * CC + c);
                        float2 p0 = *(const float2*)(g_Pc + (size_t)nbr0 * CC + c);
                        float2 p1 = *(const float2*)(g_Pc + (size_t)nbr1 * CC + c);
                        a0v[nt][0] = pa.x + p0.x; a0v[nt][1] = pa.y + p0.y;
                        b0v[nt][0] = pa.x + p1.x; b0v[nt][1] = pa.y + p1.y;
                    }
                } else {
#pragma unroll
                    for (int nt = 0; nt < 4; ++nt) {
                        int c = n0 + nt * 8 + t * 2;
                        a0v[nt][0] = s_b2[c]; a0v[nt][1] = s_b2[c + 1];
                        b0v[nt][0] = a0v[nt][0]; b0v[nt][1] = a0v[nt][1];
                    }
                }
#pragma unroll
                for (int nt = 0; nt < 4; ++nt) {
                    int c = n0 + nt * 8 + t * 2;
                    int w0 = r_lo * A_STRIDE_W + c / 2;
                    int w1 = r_hi * A_STRIDE_W + c / 2;
                    smA[w0] = pack_h2(gelu_f(acc[nt][0] + a0v[nt][0]),
                                      gelu_f(acc[nt][1] + a0v[nt][1]));
                    smA[w1] = pack_h2(gelu_f(acc[nt][2] + b0v[nt][0]),
                                      gelu_f(acc[nt][3] + b0v[nt][1]));
                }
                __syncthreads();
            } else if (!EDGE_OUT) {
                float mlo = mask_attend[node * KK + r_lo];
                float mhi = mask_attend[node * KK + r_hi];
                float cs[8];
#pragma unroll
                for (int nt = 0; nt < 4; ++nt) {
                    int c = n0 + nt * 8 + t * 2;
                    cs[nt * 2 + 0] = mlo * (acc[nt][0] + s_b3[c]) +
                                     mhi * (acc[nt][2] + s_b3[c]);
                    cs[nt * 2 + 1] = mlo * (acc[nt][1] + s_b3[c + 1]) +
                                     mhi * (acc[nt][3] + s_b3[c + 1]);
                }
#pragma unroll
                for (int off = 4; off <= 16; off <<= 1)
#pragma unroll
                    for (int j = 0; j < 8; ++j)
                        cs[j] += __shfl_xor_sync(0xffffffffu, cs[j], off);
                if (g == 0) {
#pragma unroll
                    for (int nt = 0; nt < 4; ++nt) {
                        int c = n0 + nt * 8 + t * 2;
                        s_part[mtile * CC + c] = cs[nt * 2];
                        s_part[mtile * CC + c + 1] = cs[nt * 2 + 1];
                    }
                }
                __syncthreads();
                if (tid < CC)
                    g_dh[(size_t)node * CC + tid] =
                        s_part[tid] + s_part[CC + tid] + s_part[2 * CC + tid];
            } else {
                const float* he = h_E + (size_t)node * (KK * CC);
                float v[4][4];
                float sl = 0.0f, ql = 0.0f, sh = 0.0f, qh = 0.0f;
#pragma unroll
                for (int nt = 0; nt < 4; ++nt) {
                    int c = n0 + nt * 8 + t * 2;
                    float2 e0 = *(const float2*)(he + r_lo * CC + c);
                    float2 e1 = *(const float2*)(he + r_hi * CC + c);
                    v[nt][0] = acc[nt][0] + s_b3[c] + e0.x;
                    v[nt][1] = acc[nt][1] + s_b3[c + 1] + e0.y;
                    v[nt][2] = acc[nt][2] + s_b3[c] + e1.x;
                    v[nt][3] = acc[nt][3] + s_b3[c + 1] + e1.y;
                    sl += v[nt][0] + v[nt][1]; ql += v[nt][0] * v[nt][0] + v[nt][1] * v[nt][1];
                    sh += v[nt][2] + v[nt][3]; qh += v[nt][2] * v[nt][2] + v[nt][3] * v[nt][3];
                }
#pragma unroll
                for (int off = 1; off <= 2; off <<= 1) {
                    sl += __shfl_xor_sync(0xffffffffu, sl, off);
                    ql += __shfl_xor_sync(0xffffffffu, ql, off);
                    sh += __shfl_xor_sync(0xffffffffu, sh, off);
                    qh += __shfl_xor_sync(0xffffffffu, qh, off);
                }
                if (t == 0) {
                    s_red[(r_lo * 4 + nchunk) * 2 + 0] = sl;
                    s_red[(r_lo * 4 + nchunk) * 2 + 1] = ql;
                    s_red[(r_hi * 4 + nchunk) * 2 + 0] = sh;
                    s_red[(r_hi * 4 + nchunk) * 2 + 1] = qh;
                }
                __syncthreads();
                float S0 = 0, Q0 = 0, S1 = 0, Q1 = 0;
#pragma unroll
                for (int w = 0; w < 4; ++w) {
                    S0 += s_red[(r_lo * 4 + w) * 2 + 0]; Q0 += s_red[(r_lo * 4 + w) * 2 + 1];
                    S1 += s_red[(r_hi * 4 + w) * 2 + 0]; Q1 += s_red[(r_hi * 4 + w) * 2 + 1];
                }
                float m0f = S0 * (1.0f / 128.0f);
                float rs0 = rsqrtf(Q0 * (1.0f / 128.0f) - m0f * m0f + EPSLN);
                float m1f = S1 * (1.0f / 128.0f);
                float rs1 = rsqrtf(Q1 * (1.0f / 128.0f) - m1f * m1f + EPSLN);
                float* op = outp + (size_t)node * (KK * CC);
#pragma unroll
                for (int nt = 0; nt < 4; ++nt) {
                    int c = n0 + nt * 8 + t * 2;
                    float2 o0, o1;
                    o0.x = s_g3[c] * (v[nt][0] - m0f) * rs0 + s_bl[c];
                    o0.y = s_g3[c + 1] * (v[nt][1] - m0f) * rs0 + s_bl[c + 1];
                    o1.x = s_g3[c] * (v[nt][2] - m1f) * rs1 + s_bl[c];
                    o1.y = s_g3[c + 1] * (v[nt][3] - m1f) * rs1 + s_bl[c + 1];
                    *(float2*)(op + r_lo * CC + c) = o0;
                    *(float2*)(op + r_hi * CC + c) = o1;
                }
            }
        }
    }
}

// ---------------------------------------------------------------------------
// HMMA FFN kernel: 16 nodes/block, 256 blocks, 128 threads (4 warps).
// ---------------------------------------------------------------------------
#define FA_STRIDE 68                  // A words/row (128 cols fp16)
#define FT_STRIDE 260                 // T words/row (512 cols fp16 + pad)
#define SMEM_FFN_DYN ((8192 + 16 * FA_STRIDE + 16 * FT_STRIDE + 2048) * 4)

__global__ void __launch_bounds__(128, 3) ffn_mma_kernel(
    const float* __restrict__ hV,
    const float* __restrict__ Win_b, const float* __restrict__ Wout_b,
    const float* __restrict__ g1, const float* __restrict__ b1,
    const float* __restrict__ g2, const float* __restrict__ b2,
    const float* __restrict__ mask_V, float* __restrict__ out) {
    extern __shared__ uint32_t smu[];
    uint32_t* smW = smu;                         // 8192 words (32KB slab)
    uint32_t* smA = smu + 8192;                  // 16 x 68
    uint32_t* smT = smu + 8192 + 16 * FA_STRIDE; // 16 x 260
    float* smV1 = (float*)(smu + 8192 + 16 * FA_STRIDE + 16 * FT_STRIDE); // 16x128

    __shared__ float s_red[16][4][2];

    const int tid = threadIdx.x, lane = tid & 31, wid = tid >> 5;
    const int g = lane >> 2, t = lane & 3;
    const int node0 = blockIdx.x * 16;
    const int r_lo = g, r_hi = g + 8;

    // ---- LN1: x = hV + dh/30 ; V1 = LN(x;g1,b1). warp wid rows wid*4..+3.
#pragma unroll
    for (int i = 0; i < 4; ++i) {
        int r = wid * 4 + i;
        size_t off = (size_t)(node0 + r) * CC + lane * 4;
        float4 xv = *(const float4*)(hV + off);
        float4 dv = *(const float4*)(g_dh + off);
        float x0 = xv.x + dv.x * INV_SCALE, x1 = xv.y + dv.y * INV_SCALE;
        float x2 = xv.z + dv.z * INV_SCALE, x3 = xv.w + dv.w * INV_SCALE;
        float s = x0 + x1 + x2 + x3;
        float q = x0 * x0 + x1 * x1 + x2 * x2 + x3 * x3;
#pragma unroll
        for (int o = 16; o; o >>= 1) {
            s += __shfl_xor_sync(0xffffffffu, s, o);
            q += __shfl_xor_sync(0xffffffffu, q, o);
        }
        float mean = s * (1.0f / 128.0f);
        float var = q * (1.0f / 128.0f) - mean * mean;
        float rs = rsqrtf(var + EPSLN);
        int c = lane * 4;
        float o0 = g1[c + 0] * (x0 - mean) * rs + b1[c + 0];
        float o1 = g1[c + 1] * (x1 - mean) * rs + b1[c + 1];
        float o2 = g1[c + 2] * (x2 - mean) * rs + b1[c + 2];
        float o3 = g1[c + 3] * (x3 - mean) * rs + b1[c + 3];
        *(float4*)(smV1 + r * CC + c) = make_float4(o0, o1, o2, o3);
        smA[r * FA_STRIDE + lane * 2] = pack_h2(o0, o1);
        smA[r * FA_STRIDE + lane * 2 + 1] = pack_h2(o2, o3);
    }
    __syncthreads();

    // ---- GEMM1: T = gelu(V1 @ Win + b), 4 ng slabs of N=128
    for (int ng = 0; ng < 4; ++ng) {
        if (ng) __syncthreads();   // smW reuse
        {
            const float4* src = (const float4*)(g_WimgF + ng * 16384);
            float4* dst = (float4*)smW;
#pragma unroll
            for (int i = 0; i < 16; ++i) dst[tid + 128 * i] = src[tid + 128 * i];
        }
        __syncthreads();
        float acc[4][4];
#pragma unroll
        for (int nt = 0; nt < 4; ++nt)
#pragma unroll
            for (int j = 0; j < 4; ++j) acc[nt][j] = 0.0f;
#pragma unroll
        for (int ks = 0; ks < 8; ++ks) {
            uint32_t a[4];
            int aw = r_lo * FA_STRIDE + ks * 8 + t;
            int aw2 = r_hi * FA_STRIDE + ks * 8 + t;
            a[0] = smA[aw];     a[1] = smA[aw2];
            a[2] = smA[aw + 4]; a[3] = smA[aw2 + 4];
#pragma unroll
            for (int nt = 0; nt < 4; ++nt) {
                int chunk = (wid * 4 + nt) * 8 + ks;
                uint2 bh = ((const uint2*)smW)[chunk * 32 + lane];
                mma16816(acc[nt], a, bh.x, bh.y);
            }
        }
        // epilogue: bias + gelu -> T fp16
#pragma unroll
        for (int nt = 0; nt < 4; ++nt) {
            int cl = wid * 32 + nt * 8 + t * 2;
            int cgl = ng * 128 + cl;
            float bb0 = Win_b[cgl], bb1 = Win_b[cgl + 1];
            int w0 = r_lo * FT_STRIDE + (cgl >> 1);
            int w1 = r_hi * FT_STRIDE + (cgl >> 1);
            smT[w0] = pack_h2(gelu_f(acc[nt][0] + bb0), gelu_f(acc[nt][1] + bb1));
            smT[w1] = pack_h2(gelu_f(acc[nt][2] + bb0), gelu_f(acc[nt][3] + bb1));
        }
    }
    __syncthreads();

    // ---- GEMM2: Y = T @ Wout + b, 4 kt slabs of K=128
    float accY[4][4];
#pragma unroll
    for (int nt = 0; nt < 4; ++nt)
#pragma unroll
        for (int j = 0; j < 4; ++j) accY[nt][j] = 0.0f;
    for (int kt = 0; kt < 4; ++kt) {
        __syncthreads();   // smW reuse (and smT written above)
        {
            const float4* src = (const float4*)(g_WimgF + 65536 + kt * 16384);
            float4* dst = (float4*)smW;
#pragma unroll
            for (int i = 0; i < 16; ++i) dst[tid + 128 * i] = src[tid + 128 * i];
        }
        __syncthreads();
#pragma unroll
        for (int ks = 0; ks < 8; ++ks) {
            uint32_t a[4];
            int aw = r_lo * FT_STRIDE + kt * 64 + ks * 8 + t;
            int aw2 = r_hi * FT_STRIDE + kt * 64 + ks * 8 + t;
            a[0] = smT[aw];     a[1] = smT[aw2];
            a[2] = smT[aw + 4]; a[3] = smT[aw2 + 4];
#pragma unroll
            for (int nt = 0; nt < 4; ++nt) {
                int chunk = (wid * 4 + nt) * 8 + ks;
                uint2 bh = ((const uint2*)smW)[chunk * 32 + lane];
                mma16816(accY[nt], a, bh.x, bh.y);
            }
        }
    }

    // ---- final: v = V1 + Y + bout ; LN2 ; mask
    float v[4][4];
    float sl = 0.0f, ql = 0.0f, sh = 0.0f, qh = 0.0f;
#pragma unroll
    for (int nt = 0; nt < 4; ++nt) {
        int c = wid * 32 + nt * 8 + t * 2;
        float bb0 = Wout_b[c], bb1 = Wout_b[c + 1];
        v[nt][0] = accY[nt][0] + bb0 + smV1[r_lo * CC + c];
        v[nt][1] = accY[nt][1] + bb1 + smV1[r_lo * CC + c + 1];
        v[nt][2] = accY[nt][2] + bb0 + smV1[r_hi * CC + c];
        v[nt][3] = accY[nt][3] + bb1 + smV1[r_hi * CC + c + 1];
        sl += v[nt][0] + v[nt][1]; ql += v[nt][0] * v[nt][0] + v[nt][1] * v[nt][1];
        sh += v[nt][2] + v[nt][3]; qh += v[nt][2] * v[nt][2] + v[nt][3] * v[nt][3];
    }
#pragma unroll
    for (int o = 1; o <= 2; o <<= 1) {
        sl += __shfl_xor_sync(0xffffffffu, sl, o);
        ql += __shfl_xor_sync(0xffffffffu, ql, o);
        sh += __shfl_xor_sync(0xffffffffu, sh, o);
        qh += __shfl_xor_sync(0xffffffffu, qh, o);
    }
    if (t == 0) {
        s_red[r_lo][wid][0] = sl; s_red[r_lo][wid][1] = ql;
        s_red[r_hi][wid][0] = sh; s_red[r_hi][wid][1] = qh;
    }
    __syncthreads();
    float S0 = 0, Q0 = 0, S1 = 0, Q1 = 0;
#pragma unroll
    for (int w = 0; w < 4; ++w) {
        S0 += s_red[r_lo][w][0]; Q0 += s_red[r_lo][w][1];
        S1 += s_red[r_hi][w][0]; Q1 += s_red[r_hi][w][1];
    }
    float m0f = S0 * (1.0f / 128.0f);
    float rs0 = rsqrtf(Q0 * (1.0f / 128.0f) - m0f * m0f + EPSLN);
    float m1f = S1 * (1.0f / 128.0f);
    float rs1 = rsqrtf(Q1 * (1.0f / 128.0f) - m1f * m1f + EPSLN);
    float mv0 = mask_V[node0 + r_lo], mv1 = mask_V[node0 + r_hi];
#pragma unroll
    for (int nt = 0; nt < 4; ++nt) {
        int c = wid * 32 + nt * 8 + t * 2;
        float2 o0, o1;
        o0.x = (g2[c] * (v[nt][0] - m0f) * rs0 + b2[c]) * mv0;
        o0.y = (g2[c + 1] * (v[nt][1] - m0f) * rs0 + b2[c + 1]) * mv0;
        o1.x = (g2[c] * (v[nt][2] - m1f) * rs1 + b2[c]) * mv1;
        o1.y = (g2[c + 1] * (v[nt][3] - m1f) * rs1 + b2[c + 1]) * mv1;
        *(float2*)(out + (size_t)(node0 + r_lo) * CC + c) = o0;
        *(float2*)(out + (size_t)(node0 + r_hi) * CC + c) = o1;
    }
}

// ---------------------------------------------------------------------------
// Scalar node precompute — proven Round-6 version (32 nodes/block).
// ---------------------------------------------------------------------------
template <int R>
__device__ __forceinline__ void mm_tile(float acc[R][4], const float* Xs, int xstride4,
                                        const float* Ws, int r0, int lane) {
    const float4* X4 = (const float4*)Xs;
    const float4* W4 = (const float4*)Ws;
#pragma unroll 4
    for (int kq = 0; kq < 32; ++kq) {
        float4 w0 = W4[(4 * kq + 0) * 32 + lane];
        float4 w1 = W4[(4 * kq + 1) * 32 + lane];
        float4 w2 = W4[(4 * kq + 2) * 32 + lane];
        float4 w3 = W4[(4 * kq + 3) * 32 + lane];
#pragma unroll
        for (int i = 0; i < R; ++i) {
            float4 x = X4[(r0 + i) * xstride4 + kq];
            acc[i][0] = fmaf(x.x, w0.x, acc[i][0]); acc[i][1] = fmaf(x.x, w0.y, acc[i][1]);
            acc[i][2] = fmaf(x.x, w0.z, acc[i][2]); acc[i][3] = fmaf(x.x, w0.w, acc[i][3]);
            acc[i][0] = fmaf(x.y, w1.x, acc[i][0]); acc[i][1] = fmaf(x.y, w1.y, acc[i][1]);
            acc[i][2] = fmaf(x.y, w1.z, acc[i][2]); acc[i][3] = fmaf(x.y, w1.w, acc[i][3]);
            acc[i][0] = fmaf(x.z, w2.x, acc[i][0]); acc[i][1] = fmaf(x.z, w2.y, acc[i][1]);
            acc[i][2] = fmaf(x.z, w2.z, acc[i][2]); acc[i][3] = fmaf(x.z, w2.w, acc[i][3]);
            acc[i][0] = fmaf(x.w, w3.x, acc[i][0]); acc[i][1] = fmaf(x.w, w3.y, acc[i][1]);
            acc[i][2] = fmaf(x.w, w3.z, acc[i][2]); acc[i][3] = fmaf(x.w, w3.w, acc[i][3]);
        }
    }
}

__global__ void __launch_bounds__(512) nodepre_kernel(
    const float* __restrict__ hV, const float* __restrict__ W1,
    const float* __restrict__ b1) {
    extern __shared__ float sm[];
    float* Vs = sm;
    float* Ws = sm + 4096;
    int tid = threadIdx.x, lane = tid & 31, warp = tid >> 5;
    size_t base = (size_t)blockIdx.x * 32 * CC;
    {
        const float4* src = (const float4*)(hV + base);
        float4* dst = (float4*)Vs;
#pragma unroll
        for (int e = 0; e < 2; ++e) dst[tid + 512 * e] = src[tid + 512 * e];
    }
    {
        const float4* src = (const float4*)W1;
        float4* dst = (float4*)Ws;
#pragma unroll
        for (int e = 0; e < 8; ++e) dst[tid + 512 * e] = src[tid + 512 * e];
    }
    __syncthreads();
    int r0 = warp * 2, c0 = lane * 4;
    float acc[2][4];
#pragma unroll
    for (int j = 0; j < 4; ++j) { float b = b1[c0 + j]; acc[0][j] = b; acc[1][j] = b; }
    mm_tile<2>(acc, Vs, 32, Ws, r0, lane);
#pragma unroll
    for (int i = 0; i < 2; ++i)
#pragma unroll
        for (int j = 0; j < 4; ++j)
            g_Pa[base + (size_t)(r0 + i) * CC + c0 + j] = acc[i][j];
    __syncthreads();
    {
        const float4* src = (const float4*)(W1 + 2 * CC * CC);
        float4* dst = (float4*)Ws;
#pragma unroll
        for (int e = 0; e < 8; ++e) dst[tid + 512 * e] = src[tid + 512 * e];
    }
    __syncthreads();
#pragma unroll
    for (int i = 0; i < 2; ++i)
#pragma unroll
        for (int j = 0; j < 4; ++j) acc[i][j] = 0.0f;
    mm_tile<2>(acc, Vs, 32, Ws, r0, lane);
#pragma unroll
    for (int i = 0; i < 2; ++i)
#pragma unroll
        for (int j = 0; j < 4; ++j)
            g_Pc[base + (size_t)(r0 + i) * CC + c0 + j] = acc[i][j];
}

// ---------------------------------------------------------------------------
extern "C" void kernel_launch(void* const* d_in, const int* in_sizes, int n_in,
                              void* d_out, int out_size) {
    const float* h_V = (const float*)d_in[0];
    const float* h_E = (const float*)d_in[1];
    const int* E_idx = (const int*)d_in[2];
    const float* mask_V = (const float*)d_in[3];
    const float* mask_attend = (const float*)d_in[4];
    const float* W1_w = (const float*)d_in[5];
    const float* W1_b = (const float*)d_in[6];
    const float* W2_w = (const float*)d_in[7];
    const float* W2_b = (const float*)d_in[8];
    const float* W3_w = (const float*)d_in[9];
    const float* W3_b = (const float*)d_in[10];
    const float* W11_w = (const float*)d_in[11];
    const float* W11_b = (const float*)d_in[12];
    const float* W12_w = (const float*)d_in[13];
    const float* W12_b = (const float*)d_in[14];
    const float* W13_w = (const float*)d_in[15];
    const float* W13_b = (const float*)d_in[16];
    const float* Win_w = (const float*)d_in[17];
    const float* Win_b = (const float*)d_in[18];
    const float* Wout_w = (const float*)d_in[19];
    const float* Wout_b = (const float*)d_in[20];
    const float* g1 = (const float*)d_in[21];
    const float* b1 = (const float*)d_in[22];
    const float* g2 = (const float*)d_in[23];
    const float* b2 = (const float*)d_in[24];
    const float* g3 = (const float*)d_in[25];
    const float* b3 = (const float*)d_in[26];

    float* out_hV = (float*)d_out;
    float* out_hE = out_hV + (size_t)BN * CC;

    const int SMEM_PRE = (4096 + 16384) * 4;

    cudaFuncSetAttribute(nodepre_kernel, cudaFuncAttributeMaxDynamicSharedMemorySize, SMEM_PRE);
    cudaFuncSetAttribute(ffn_mma_kernel, cudaFuncAttributeMaxDynamicSharedMemorySize, SMEM_FFN_DYN);
    cudaFuncSetAttribute(edge_mma_kernel<false>, cudaFuncAttributeMaxDynamicSharedMemorySize, SMEM_EDGE_DYN);
    cudaFuncSetAttribute(edge_mma_kernel<true>, cudaFuncAttributeMaxDynamicSharedMemorySize, SMEM_EDGE_DYN);

    prep_weights<<<6, 256>>>(W1_w + CC * CC, W2_w, W3_w, W11_w + CC * CC, W12_w, W13_w);
    prep_ffn_weights<<<2, 256>>>(Win_w, Wout_w);
    nodepre_kernel<<<BN / 32, 512, SMEM_PRE>>>(h_V, W1_w, W1_b);
    edge_mma_kernel<false><<<296, 384, SMEM_EDGE_DYN>>>(h_E, E_idx, mask_attend, 0,
                                                        W2_b, W3_b, g3, b3, out_hE);
    ffn_mma_kernel<<<BN / 16, 128, SMEM_FFN_DYN>>>(h_V, Win_b, Wout_b,
                                                   g1, b1, g2, b2, mask_V, out_hV);
    nodepre_kernel<<<BN / 32, 512, SMEM_PRE>>>(out_hV, W11_w, W11_b);
    edge_mma_kernel<true><<<296, 384, SMEM_EDGE_DYN>>>(h_E, E_idx, mask_attend, 1,
                                                       W12_b, W13_b, g3, b3, out_hE);
}

// round 16
// speedup vs baseline: 1.1125x; 1.1125x over previous
#include <cuda_runtime.h>
#include <cuda_fp16.h>
#include <math.h>
#include <stdint.h>

#define BB 2
#define NN 2048
#define KK 48
#define CC 128
#define FFD 512
#define BN (BB * NN)
#define EPSLN 1e-5f
#define INV_SCALE (1.0f / 30.0f)

// ---------------- device scratch ----------------
__device__ float g_Pa[BN * CC];
__device__ float g_Pc[BN * CC];
__device__ float g_dh[BN * CC];
__device__ __half g_Wimg[6 * 16384];
__device__ __half g_WimgF[2 * 65536];

__device__ __forceinline__ float gelu_f(float x) {
    return 0.5f * x * (1.0f + erff(x * 0.70710678118654752f));
}
__device__ __forceinline__ uint32_t pack_h2(float a, float b) {
    __half2 h; h.x = __float2half_rn(a); h.y = __float2half_rn(b);
    return *reinterpret_cast<uint32_t*>(&h);
}
__device__ __forceinline__ void mma16816(float c[4], const uint32_t a[4],
                                         uint32_t b0, uint32_t b1) {
    asm volatile(
        "mma.sync.aligned.m16n8k16.row.col.f32.f16.f16.f32 "
        "{%0,%1,%2,%3}, {%4,%5,%6,%7}, {%8,%9}, {%0,%1,%2,%3};"
        : "+f"(c[0]), "+f"(c[1]), "+f"(c[2]), "+f"(c[3])
        : "r"(a[0]), "r"(a[1]), "r"(a[2]), "r"(a[3]), "r"(b0), "r"(b1));
}

// ---------------------------------------------------------------------------
// Edge weight prep (6 images, proven layout).
// ---------------------------------------------------------------------------
__global__ void prep_weights(const float* __restrict__ A0, const float* __restrict__ A1,
                             const float* __restrict__ A2, const float* __restrict__ B0,
                             const float* __restrict__ B1, const float* __restrict__ B2) {
    const float* srcs[6] = {A0, A1, A2, B0, B1, B2};
    int img = blockIdx.x;
    const float* s = srcs[img];
    __half* dst = g_Wimg + (size_t)img * 16384;
    for (int e = threadIdx.x; e < 16384; e += blockDim.x) {
        int k = e >> 7, n = e & 127;
        int kk = k & 15;
        int t = (kk & 7) >> 1, hi8 = kk >> 3, idx = kk & 1;
        int lane = (n & 7) * 4 + t;
        int chunk = (n >> 3) * 8 + (k >> 4);
        dst[chunk * 128 + lane * 4 + hi8 * 2 + idx] = __float2half_rn(s[e]);
    }
}

// FFN weight prep — 64 blocks: blocks 0..31 Win, 32..63 Wout (2048 elems/block).
__global__ void prep_ffn_weights(const float* __restrict__ Win,
                                 const float* __restrict__ Wout) {
    int b = blockIdx.x;
    if (b < 32) {
        int base = b * 2048;
        for (int i = threadIdx.x; i < 2048; i += blockDim.x) {
            int e = base + i;
            int k = e >> 9, n = e & 511;          // Win[k][n]
            int ng = n >> 7, n1 = n & 127;
            int kk = k & 15;
            int t = (kk & 7) >> 1, hi8 = kk >> 3, idx = kk & 1;
            int lane = (n1 & 7) * 4 + t;
            int chunk = (n1 >> 3) * 8 + (k >> 4);
            g_WimgF[ng * 16384 + chunk * 128 + lane * 4 + hi8 * 2 + idx] =
                __float2half_rn(Win[e]);
        }
    } else {
        int base = (b - 32) * 2048;
        for (int i = threadIdx.x; i < 2048; i += blockDim.x) {
            int e = base + i;
            int k = e >> 7, n = e & 127;          // Wout[k][n]
            int kt = k >> 7, k1 = k & 127;
            int kk = k1 & 15;
            int t = (kk & 7) >> 1, hi8 = kk >> 3, idx = kk & 1;
            int lane = (n & 7) * 4 + t;
            int chunk = (n >> 3) * 8 + (k1 >> 4);
            g_WimgF[65536 + kt * 16384 + chunk * 128 + lane * 4 + hi8 * 2 + idx] =
                __float2half_rn(Wout[e]);
        }
    }
}

// ---------------------------------------------------------------------------
// HMMA edge MLP — byte-identical to Round 12/15 (proven).
// ---------------------------------------------------------------------------
#define A_STRIDE_W 68
#define A_WORDS (KK * A_STRIDE_W)
#define SMEM_W_BYTES 98304
#define SMEM_EDGE_DYN (SMEM_W_BYTES + A_WORDS * 4)

template <bool EDGE_OUT>
__global__ void __launch_bounds__(384, 2) edge_mma_kernel(
    const float* __restrict__ h_E, const int* __restrict__ E_idx,
    const float* __restrict__ mask_attend, int wset,
    const float* __restrict__ b2v, const float* __restrict__ b3v,
    const float* __restrict__ g3v, const float* __restrict__ b3ln,
    float* __restrict__ outp) {
    extern __shared__ uint32_t smem[];
    uint32_t* smW = smem;
    uint32_t* smA = smem + (SMEM_W_BYTES / 4);

    __shared__ float s_b2[CC], s_b3[CC], s_g3[CC], s_bl[CC];
    __shared__ float s_red[KK * 4 * 2];
    float* s_part = s_red;

    const int tid = threadIdx.x, lane = tid & 31, wid = tid >> 5;
    const int g = lane >> 2, t = lane & 3;
    const int mtile = wid >> 2, nchunk = wid & 3;
    const int m0 = mtile * 16, n0 = nchunk * 32;
    const int ntg0 = nchunk * 4;

    {
        const float4* src = (const float4*)(g_Wimg + (size_t)wset * 3 * 16384);
        float4* dst = (float4*)smW;
        for (int i = tid; i < 6144; i += 384) dst[i] = src[i];
    }
    if (tid < CC) {
        s_b2[tid] = b2v[tid];
        s_b3[tid] = b3v[tid];
        if (EDGE_OUT) { s_g3[tid] = g3v[tid]; s_bl[tid] = b3ln[tid]; }
    }

    const int r_lo = m0 + g, r_hi = m0 + g + 8;

    for (int node = blockIdx.x; node < BN; node += gridDim.x) {
        __syncthreads();

#pragma unroll
        for (int i = 0; i < 4; ++i) {
            int idx4 = tid + 384 * i;
            float4 v = ((const float4*)(h_E + (size_t)node * (KK * CC)))[idx4];
            int row = idx4 >> 5, colw = (idx4 & 31) * 2;
            int w = row * A_STRIDE_W + colw;
            smA[w] = pack_h2(v.x, v.y);
            smA[w + 1] = pack_h2(v.z, v.w);
        }
        __syncthreads();

        for (int layer = 0; layer < 3; ++layer) {
            float acc[4][4];
#pragma unroll
            for (int nt = 0; nt < 4; ++nt)
#pragma unroll
                for (int j = 0; j < 4; ++j) acc[nt][j] = 0.0f;

            const uint2* WH = (const uint2*)smW + layer * 4096;
#pragma unroll
            for (int ks = 0; ks < 8; ++ks) {
                uint32_t a[4];
                int aw = r_lo * A_STRIDE_W + ks * 8 + t;
                int aw2 = r_hi * A_STRIDE_W + ks * 8 + t;
                a[0] = smA[aw];     a[1] = smA[aw2];
                a[2] = smA[aw + 4]; a[3] = smA[aw2 + 4];
#pragma unroll
                for (int nt = 0; nt < 4; ++nt) {
                    int chunk = (ntg0 + nt) * 8 + ks;
                    uint2 bh = WH[chunk * 32 + lane];
                    mma16816(acc[nt], a, bh.x, bh.y);
                }
            }
            __syncthreads();

            if (layer < 2) {
                float a0v[4][2], b0v[4][2];
                if (layer == 0) {
                    int gb = (node >> 11) * NN;
                    int nbr0 = gb + E_idx[node * KK + r_lo];
                    int nbr1 = gb + E_idx[node * KK + r_hi];
#pragma unroll
                    for (int nt = 0; nt < 4; ++nt) {
                        int c = n0 + nt * 8 + t * 2;
                        float2 pa = *(const float2*)(g_Pa + (size_t)node * CC + c);
                        float2 p0 = *(const float2*)(g_Pc + (size_t)nbr0 * CC + c);
                        float2 p1 = *(const float2*)(g_Pc + (size_t)nbr1 * CC + c);
                        a0v[nt][0] = pa.x + p0.x; a0v[nt][1] = pa.y + p0.y;
                        b0v[nt][0] = pa.x + p1.x; b0v[nt][1] = pa.y + p1.y;
                    }
                } else {
#pragma unroll
                    for (int nt = 0; nt < 4; ++nt) {
                        int c = n0 + nt * 8 + t * 2;
                        a0v[nt][0] = s_b2[c]; a0v[nt][1] = s_b2[c + 1];
                        b0v[nt][0] = a0v[nt][0]; b0v[nt][1] = a0v[nt][1];
                    }
                }
#pragma unroll
                for (int nt = 0; nt < 4; ++nt) {
                    int c = n0 + nt * 8 + t * 2;
                    int w0 = r_lo * A_STRIDE_W + c / 2;
                    int w1 = r_hi * A_STRIDE_W + c / 2;
                    smA[w0] = pack_h2(gelu_f(acc[nt][0] + a0v[nt][0]),
                                      gelu_f(acc[nt][1] + a0v[nt][1]));
                    smA[w1] = pack_h2(gelu_f(acc[nt][2] + b0v[nt][0]),
                                      gelu_f(acc[nt][3] + b0v[nt][1]));
                }
                __syncthreads();
            } else if (!EDGE_OUT) {
                float mlo = mask_attend[node * KK + r_lo];
                float mhi = mask_attend[node * KK + r_hi];
                float cs[8];
#pragma unroll
                for (int nt = 0; nt < 4; ++nt) {
                    int c = n0 + nt * 8 + t * 2;
                    cs[nt * 2 + 0] = mlo * (acc[nt][0] + s_b3[c]) +
                                     mhi * (acc[nt][2] + s_b3[c]);
                    cs[nt * 2 + 1] = mlo * (acc[nt][1] + s_b3[c + 1]) +
                                     mhi * (acc[nt][3] + s_b3[c + 1]);
                }
#pragma unroll
                for (int off = 4; off <= 16; off <<= 1)
#pragma unroll
                    for (int j = 0; j < 8; ++j)
                        cs[j] += __shfl_xor_sync(0xffffffffu, cs[j], off);
                if (g == 0) {
#pragma unroll
                    for (int nt = 0; nt < 4; ++nt) {
                        int c = n0 + nt * 8 + t * 2;
                        s_part[mtile * CC + c] = cs[nt * 2];
                        s_part[mtile * CC + c + 1] = cs[nt * 2 + 1];
                    }
                }
                __syncthreads();
                if (tid < CC)
                    g_dh[(size_t)node * CC + tid] =
                        s_part[tid] + s_part[CC + tid] + s_part[2 * CC + tid];
            } else {
                const float* he = h_E + (size_t)node * (KK * CC);
                float v[4][4];
                float sl = 0.0f, ql = 0.0f, sh = 0.0f, qh = 0.0f;
#pragma unroll
                for (int nt = 0; nt < 4; ++nt) {
                    int c = n0 + nt * 8 + t * 2;
                    float2 e0 = *(const float2*)(he + r_lo * CC + c);
                    float2 e1 = *(const float2*)(he + r_hi * CC + c);
                    v[nt][0] = acc[nt][0] + s_b3[c] + e0.x;
                    v[nt][1] = acc[nt][1] + s_b3[c + 1] + e0.y;
                    v[nt][2] = acc[nt][2] + s_b3[c] + e1.x;
                    v[nt][3] = acc[nt][3] + s_b3[c + 1] + e1.y;
                    sl += v[nt][0] + v[nt][1]; ql += v[nt][0] * v[nt][0] + v[nt][1] * v[nt][1];
                    sh += v[nt][2] + v[nt][3]; qh += v[nt][2] * v[nt][2] + v[nt][3] * v[nt][3];
                }
#pragma unroll
                for (int off = 1; off <= 2; off <<= 1) {
                    sl += __shfl_xor_sync(0xffffffffu, sl, off);
                    ql += __shfl_xor_sync(0xffffffffu, ql, off);
                    sh += __shfl_xor_sync(0xffffffffu, sh, off);
                    qh += __shfl_xor_sync(0xffffffffu, qh, off);
                }
                if (t == 0) {
                    s_red[(r_lo * 4 + nchunk) * 2 + 0] = sl;
                    s_red[(r_lo * 4 + nchunk) * 2 + 1] = ql;
                    s_red[(r_hi * 4 + nchunk) * 2 + 0] = sh;
                    s_red[(r_hi * 4 + nchunk) * 2 + 1] = qh;
                }
                __syncthreads();
                float S0 = 0, Q0 = 0, S1 = 0, Q1 = 0;
#pragma unroll
                for (int w = 0; w < 4; ++w) {
                    S0 += s_red[(r_lo * 4 + w) * 2 + 0]; Q0 += s_red[(r_lo * 4 + w) * 2 + 1];
                    S1 += s_red[(r_hi * 4 + w) * 2 + 0]; Q1 += s_red[(r_hi * 4 + w) * 2 + 1];
                }
                float m0f = S0 * (1.0f / 128.0f);
                float rs0 = rsqrtf(Q0 * (1.0f / 128.0f) - m0f * m0f + EPSLN);
                float m1f = S1 * (1.0f / 128.0f);
                float rs1 = rsqrtf(Q1 * (1.0f / 128.0f) - m1f * m1f + EPSLN);
                float* op = outp + (size_t)node * (KK * CC);
#pragma unroll
                for (int nt = 0; nt < 4; ++nt) {
                    int c = n0 + nt * 8 + t * 2;
                    float2 o0, o1;
                    o0.x = s_g3[c] * (v[nt][0] - m0f) * rs0 + s_bl[c];
                    o0.y = s_g3[c + 1] * (v[nt][1] - m0f) * rs0 + s_bl[c + 1];
                    o1.x = s_g3[c] * (v[nt][2] - m1f) * rs1 + s_bl[c];
                    o1.y = s_g3[c + 1] * (v[nt][3] - m1f) * rs1 + s_bl[c + 1];
                    *(float2*)(op + r_lo * CC + c) = o0;
                    *(float2*)(op + r_hi * CC + c) = o1;
                }
            }
        }
    }
}

// ---------------------------------------------------------------------------
// HMMA FFN kernel v2: 32 nodes/block, 128 blocks, 256 threads (8 warps).
// Warp (mtile = wid>>2, nchunk = wid&3). SMEM ~89KB -> 2 CTA/SM.
// ---------------------------------------------------------------------------
#define FA_STRIDE 68
#define FT_STRIDE 260
#define SMEM_FFN_DYN ((8192 + 32 * FA_STRIDE + 32 * FT_STRIDE + 4096) * 4)

__global__ void __launch_bounds__(256, 2) ffn_mma_kernel(
    const float* __restrict__ hV,
    const float* __restrict__ Win_b, const float* __restrict__ Wout_b,
    const float* __restrict__ g1, const float* __restrict__ b1,
    const float* __restrict__ g2, const float* __restrict__ b2,
    const float* __restrict__ mask_V, float* __restrict__ out) {
    extern __shared__ uint32_t smu[];
    uint32_t* smW = smu;                          // 8192 words
    uint32_t* smA = smu + 8192;                   // 32 x 68
    uint32_t* smT = smu + 8192 + 32 * FA_STRIDE;  // 32 x 260
    float* smV1 = (float*)(smu + 8192 + 32 * FA_STRIDE + 32 * FT_STRIDE); // 32x128

    __shared__ float s_red[32][4][2];

    const int tid = threadIdx.x, lane = tid & 31, wid = tid >> 5;
    const int g = lane >> 2, t = lane & 3;
    const int mtile = wid >> 2, nchunk = wid & 3;
    const int node0 = blockIdx.x * 32;
    const int r_lo = mtile * 16 + g, r_hi = r_lo + 8;

    // ---- LN1: rows wid*4 .. wid*4+3 (8 warps x 4 = 32 rows)
#pragma unroll
    for (int i = 0; i < 4; ++i) {
        int r = wid * 4 + i;
        size_t off = (size_t)(node0 + r) * CC + lane * 4;
        float4 xv = *(const float4*)(hV + off);
        float4 dv = *(const float4*)(g_dh + off);
        float x0 = xv.x + dv.x * INV_SCALE, x1 = xv.y + dv.y * INV_SCALE;
        float x2 = xv.z + dv.z * INV_SCALE, x3 = xv.w + dv.w * INV_SCALE;
        float s = x0 + x1 + x2 + x3;
        float q = x0 * x0 + x1 * x1 + x2 * x2 + x3 * x3;
#pragma unroll
        for (int o = 16; o; o >>= 1) {
            s += __shfl_xor_sync(0xffffffffu, s, o);
            q += __shfl_xor_sync(0xffffffffu, q, o);
        }
        float mean = s * (1.0f / 128.0f);
        float var = q * (1.0f / 128.0f) - mean * mean;
        float rs = rsqrtf(var + EPSLN);
        int c = lane * 4;
        float o0 = g1[c + 0] * (x0 - mean) * rs + b1[c + 0];
        float o1 = g1[c + 1] * (x1 - mean) * rs + b1[c + 1];
        float o2 = g1[c + 2] * (x2 - mean) * rs + b1[c + 2];
        float o3 = g1[c + 3] * (x3 - mean) * rs + b1[c + 3];
        *(float4*)(smV1 + r * CC + c) = make_float4(o0, o1, o2, o3);
        smA[r * FA_STRIDE + lane * 2] = pack_h2(o0, o1);
        smA[r * FA_STRIDE + lane * 2 + 1] = pack_h2(o2, o3);
    }
    __syncthreads();

    // ---- GEMM1: T = gelu(V1 @ Win + b), 4 ng slabs of N=128
    for (int ng = 0; ng < 4; ++ng) {
        if (ng) __syncthreads();
        {
            const float4* src = (const float4*)(g_WimgF + ng * 16384);
            float4* dst = (float4*)smW;
#pragma unroll
            for (int i = 0; i < 8; ++i) dst[tid + 256 * i] = src[tid + 256 * i];
        }
        __syncthreads();
        float acc[4][4];
#pragma unroll
        for (int nt = 0; nt < 4; ++nt)
#pragma unroll
            for (int j = 0; j < 4; ++j) acc[nt][j] = 0.0f;
#pragma unroll
        for (int ks = 0; ks < 8; ++ks) {
            uint32_t a[4];
            int aw = r_lo * FA_STRIDE + ks * 8 + t;
            int aw2 = r_hi * FA_STRIDE + ks * 8 + t;
            a[0] = smA[aw];     a[1] = smA[aw2];
            a[2] = smA[aw + 4]; a[3] = smA[aw2 + 4];
#pragma unroll
            for (int nt = 0; nt < 4; ++nt) {
                int chunk = (nchunk * 4 + nt) * 8 + ks;
                uint2 bh = ((const uint2*)smW)[chunk * 32 + lane];
                mma16816(acc[nt], a, bh.x, bh.y);
            }
        }
#pragma unroll
        for (int nt = 0; nt < 4; ++nt) {
            int cl = nchunk * 32 + nt * 8 + t * 2;
            int cgl = ng * 128 + cl;
            float bb0 = Win_b[cgl], bb1 = Win_b[cgl + 1];
            int w0 = r_lo * FT_STRIDE + (cgl >> 1);
            int w1 = r_hi * FT_STRIDE + (cgl >> 1);
            smT[w0] = pack_h2(gelu_f(acc[nt][0] + bb0), gelu_f(acc[nt][1] + bb1));
            smT[w1] = pack_h2(gelu_f(acc[nt][2] + bb0), gelu_f(acc[nt][3] + bb1));
        }
    }

    // ---- GEMM2: Y = T @ Wout + b, 4 kt slabs of K=128
    float accY[4][4];
#pragma unroll
    for (int nt = 0; nt < 4; ++nt)
#pragma unroll
        for (int j = 0; j < 4; ++j) accY[nt][j] = 0.0f;
    for (int kt = 0; kt < 4; ++kt) {
        __syncthreads();   // smW reuse + smT written above
        {
            const float4* src = (const float4*)(g_WimgF + 65536 + kt * 16384);
            float4* dst = (float4*)smW;
#pragma unroll
            for (int i = 0; i < 8; ++i) dst[tid + 256 * i] = src[tid + 256 * i];
        }
        __syncthreads();
#pragma unroll
        for (int ks = 0; ks < 8; ++ks) {
            uint32_t a[4];
            int aw = r_lo * FT_STRIDE + kt * 64 + ks * 8 + t;
            int aw2 = r_hi * FT_STRIDE + kt * 64 + ks * 8 + t;
            a[0] = smT[aw];     a[1] = smT[aw2];
            a[2] = smT[aw + 4]; a[3] = smT[aw2 + 4];
#pragma unroll
            for (int nt = 0; nt < 4; ++nt) {
                int chunk = (nchunk * 4 + nt) * 8 + ks;
                uint2 bh = ((const uint2*)smW)[chunk * 32 + lane];
                mma16816(accY[nt], a, bh.x, bh.y);
            }
        }
    }

    // ---- final: v = V1 + Y + bout ; LN2 ; mask
    float v[4][4];
    float sl = 0.0f, ql = 0.0f, sh = 0.0f, qh = 0.0f;
#pragma unroll
    for (int nt = 0; nt < 4; ++nt) {
        int c = nchunk * 32 + nt * 8 + t * 2;
        float bb0 = Wout_b[c], bb1 = Wout_b[c + 1];
        v[nt][0] = accY[nt][0] + bb0 + smV1[r_lo * CC + c];
        v[nt][1] = accY[nt][1] + bb1 + smV1[r_lo * CC + c + 1];
        v[nt][2] = accY[nt][2] + bb0 + smV1[r_hi * CC + c];
        v[nt][3] = accY[nt][3] + bb1 + smV1[r_hi * CC + c + 1];
        sl += v[nt][0] + v[nt][1]; ql += v[nt][0] * v[nt][0] + v[nt][1] * v[nt][1];
        sh += v[nt][2] + v[nt][3]; qh += v[nt][2] * v[nt][2] + v[nt][3] * v[nt][3];
    }
#pragma unroll
    for (int o = 1; o <= 2; o <<= 1) {
        sl += __shfl_xor_sync(0xffffffffu, sl, o);
        ql += __shfl_xor_sync(0xffffffffu, ql, o);
        sh += __shfl_xor_sync(0xffffffffu, sh, o);
        qh += __shfl_xor_sync(0xffffffffu, qh, o);
    }
    if (t == 0) {
        s_red[r_lo][nchunk][0] = sl; s_red[r_lo][nchunk][1] = ql;
        s_red[r_hi][nchunk][0] = sh; s_red[r_hi][nchunk][1] = qh;
    }
    __syncthreads();
    float S0 = 0, Q0 = 0, S1 = 0, Q1 = 0;
#pragma unroll
    for (int w = 0; w < 4; ++w) {
        S0 += s_red[r_lo][w][0]; Q0 += s_red[r_lo][w][1];
        S1 += s_red[r_hi][w][0]; Q1 += s_red[r_hi][w][1];
    }
    float m0f = S0 * (1.0f / 128.0f);
    float rs0 = rsqrtf(Q0 * (1.0f / 128.0f) - m0f * m0f + EPSLN);
    float m1f = S1 * (1.0f / 128.0f);
    float rs1 = rsqrtf(Q1 * (1.0f / 128.0f) - m1f * m1f + EPSLN);
    float mv0 = mask_V[node0 + r_lo], mv1 = mask_V[node0 + r_hi];
#pragma unroll
    for (int nt = 0; nt < 4; ++nt) {
        int c = nchunk * 32 + nt * 8 + t * 2;
        float2 o0, o1;
        o0.x = (g2[c] * (v[nt][0] - m0f) * rs0 + b2[c]) * mv0;
        o0.y = (g2[c + 1] * (v[nt][1] - m0f) * rs0 + b2[c + 1]) * mv0;
        o1.x = (g2[c] * (v[nt][2] - m1f) * rs1 + b2[c]) * mv1;
        o1.y = (g2[c + 1] * (v[nt][3] - m1f) * rs1 + b2[c + 1]) * mv1;
        *(float2*)(out + (size_t)(node0 + r_lo) * CC + c) = o0;
        *(float2*)(out + (size_t)(node0 + r_hi) * CC + c) = o1;
    }
}

// ---------------------------------------------------------------------------
// Scalar node precompute — proven Round-6 version.
// ---------------------------------------------------------------------------
template <int R>
__device__ __forceinline__ void mm_tile(float acc[R][4], const float* Xs, int xstride4,
                                        const float* Ws, int r0, int lane) {
    const float4* X4 = (const float4*)Xs;
    const float4* W4 = (const float4*)Ws;
#pragma unroll 4
    for (int kq = 0; kq < 32; ++kq) {
        float4 w0 = W4[(4 * kq + 0) * 32 + lane];
        float4 w1 = W4[(4 * kq + 1) * 32 + lane];
        float4 w2 = W4[(4 * kq + 2) * 32 + lane];
        float4 w3 = W4[(4 * kq + 3) * 32 + lane];
#pragma unroll
        for (int i = 0; i < R; ++i) {
            float4 x = X4[(r0 + i) * xstride4 + kq];
            acc[i][0] = fmaf(x.x, w0.x, acc[i][0]); acc[i][1] = fmaf(x.x, w0.y, acc[i][1]);
            acc[i][2] = fmaf(x.x, w0.z, acc[i][2]); acc[i][3] = fmaf(x.x, w0.w, acc[i][3]);
            acc[i][0] = fmaf(x.y, w1.x, acc[i][0]); acc[i][1] = fmaf(x.y, w1.y, acc[i][1]);
            acc[i][2] = fmaf(x.y, w1.z, acc[i][2]); acc[i][3] = fmaf(x.y, w1.w, acc[i][3]);
            acc[i][0] = fmaf(x.z, w2.x, acc[i][0]); acc[i][1] = fmaf(x.z, w2.y, acc[i][1]);
            acc[i][2] = fmaf(x.z, w2.z, acc[i][2]); acc[i][3] = fmaf(x.z, w2.w, acc[i][3]);
            acc[i][0] = fmaf(x.w, w3.x, acc[i][0]); acc[i][1] = fmaf(x.w, w3.y, acc[i][1]);
            acc[i][2] = fmaf(x.w, w3.z, acc[i][2]); acc[i][3] = fmaf(x.w, w3.w, acc[i][3]);
        }
    }
}

__global__ void __launch_bounds__(512) nodepre_kernel(
    const float* __restrict__ hV, const float* __restrict__ W1,
    const float* __restrict__ b1) {
    extern __shared__ float sm[];
    float* Vs = sm;
    float* Ws = sm + 4096;
    int tid = threadIdx.x, lane = tid & 31, warp = tid >> 5;
    size_t base = (size_t)blockIdx.x * 32 * CC;
    {
        const float4* src = (const float4*)(hV + base);
        float4* dst = (float4*)Vs;
#pragma unroll
        for (int e = 0; e < 2; ++e) dst[tid + 512 * e] = src[tid + 512 * e];
    }
    {
        const float4* src = (const float4*)W1;
        float4* dst = (float4*)Ws;
#pragma unroll
        for (int e = 0; e < 8; ++e) dst[tid + 512 * e] = src[tid + 512 * e];
    }
    __syncthreads();
    int r0 = warp * 2, c0 = lane * 4;
    float acc[2][4];
#pragma unroll
    for (int j = 0; j < 4; ++j) { float b = b1[c0 + j]; acc[0][j] = b; acc[1][j] = b; }
    mm_tile<2>(acc, Vs, 32, Ws, r0, lane);
#pragma unroll
    for (int i = 0; i < 2; ++i)
#pragma unroll
        for (int j = 0; j < 4; ++j)
            g_Pa[base + (size_t)(r0 + i) * CC + c0 + j] = acc[i][j];
    __syncthreads();
    {
        const float4* src = (const float4*)(W1 + 2 * CC * CC);
        float4* dst = (float4*)Ws;
#pragma unroll
        for (int e = 0; e < 8; ++e) dst[tid + 512 * e] = src[tid + 512 * e];
    }
    __syncthreads();
#pragma unroll
    for (int i = 0; i < 2; ++i)
#pragma unroll
        for (int j = 0; j < 4; ++j) acc[i][j] = 0.0f;
    mm_tile<2>(acc, Vs, 32, Ws, r0, lane);
#pragma unroll
    for (int i = 0; i < 2; ++i)
#pragma unroll
        for (int j = 0; j < 4; ++j)
            g_Pc[base + (size_t)(r0 + i) * CC + c0 + j] = acc[i][j];
}

// ---------------------------------------------------------------------------
extern "C" void kernel_launch(void* const* d_in, const int* in_sizes, int n_in,
                              void* d_out, int out_size) {
    const float* h_V = (const float*)d_in[0];
    const float* h_E = (const float*)d_in[1];
    const int* E_idx = (const int*)d_in[2];
    const float* mask_V = (const float*)d_in[3];
    const float* mask_attend = (const float*)d_in[4];
    const float* W1_w = (const float*)d_in[5];
    const float* W1_b = (const float*)d_in[6];
    const float* W2_w = (const float*)d_in[7];
    const float* W2_b = (const float*)d_in[8];
    const float* W3_w = (const float*)d_in[9];
    const float* W3_b = (const float*)d_in[10];
    const float* W11_w = (const float*)d_in[11];
    const float* W11_b = (const float*)d_in[12];
    const float* W12_w = (const float*)d_in[13];
    const float* W12_b = (const float*)d_in[14];
    const float* W13_w = (const float*)d_in[15];
    const float* W13_b = (const float*)d_in[16];
    const float* Win_w = (const float*)d_in[17];
    const float* Win_b = (const float*)d_in[18];
    const float* Wout_w = (const float*)d_in[19];
    const float* Wout_b = (const float*)d_in[20];
    const float* g1 = (const float*)d_in[21];
    const float* b1 = (const float*)d_in[22];
    const float* g2 = (const float*)d_in[23];
    const float* b2 = (const float*)d_in[24];
    const float* g3 = (const float*)d_in[25];
    const float* b3 = (const float*)d_in[26];

    float* out_hV = (float*)d_out;
    float* out_hE = out_hV + (size_t)BN * CC;

    const int SMEM_PRE = (4096 + 16384) * 4;

    cudaFuncSetAttribute(nodepre_kernel, cudaFuncAttributeMaxDynamicSharedMemorySize, SMEM_PRE);
    cudaFuncSetAttribute(ffn_mma_kernel, cudaFuncAttributeMaxDynamicSharedMemorySize, SMEM_FFN_DYN);
    cudaFuncSetAttribute(edge_mma_kernel<false>, cudaFuncAttributeMaxDynamicSharedMemorySize, SMEM_EDGE_DYN);
    cudaFuncSetAttribute(edge_mma_kernel<true>, cudaFuncAttributeMaxDynamicSharedMemorySize, SMEM_EDGE_DYN);

    prep_weights<<<6, 256>>>(W1_w + CC * CC, W2_w, W3_w, W11_w + CC * CC, W12_w, W13_w);
    prep_ffn_weights<<<64, 256>>>(Win_w, Wout_w);
    nodepre_kernel<<<BN / 32, 512, SMEM_PRE>>>(h_V, W1_w, W1_b);
    edge_mma_kernel<false><<<296, 384, SMEM_EDGE_DYN>>>(h_E, E_idx, mask_attend, 0,
                                                        W2_b, W3_b, g3, b3, out_hE);
    ffn_mma_kernel<<<BN / 32, 256, SMEM_FFN_DYN>>>(h_V, Win_b, Wout_b,
                                                   g1, b1, g2, b2, mask_V, out_hV);
    nodepre_kernel<<<BN / 32, 512, SMEM_PRE>>>(out_hV, W11_w, W11_b);
    edge_mma_kernel<true><<<296, 384, SMEM_EDGE_DYN>>>(h_E, E_idx, mask_attend, 1,
                                                       W12_b, W13_b, g3, b3, out_hE);
}